// round 5
// baseline (speedup 1.0000x reference)
#include <cuda_runtime.h>

#define BB 64
#define SS 512
#define HH 768
#define CC 9
#define KCH 64       // chunks per batch
#define CH  8        // steps per chunk (64*8 = 512 >= 511)
#define WPBATCH 32   // scan warps per batch (2 chunks, 16 rows each)
#define L2E 1.4426950408889634f
#define LN2 0.6931471805599453f
#define FULLMASK 0xffffffffu

// scratch (no allocations allowed)
__device__ __align__(16) float g_P[BB * KCH * 81];      // 1.33 MB chunk matrices
__device__ __align__(16) int   g_esum[BB * KCH * CC];   // per-row exponents
__device__ float g_num[BB * WPBATCH];                   // numerator partials
__device__ float g_emis0[BB * CC];                      // t=0 emissions
__device__ float g_acc = 0.0f;
__device__ int   g_cnt = 0;

__device__ __forceinline__ float ex2f(float x) {
    float y; asm("ex2.approx.ftz.f32 %0, %1;" : "=f"(y) : "f"(x)); return y;
}
__device__ __forceinline__ float lg2f(float x) {
    float y; asm("lg2.approx.ftz.f32 %0, %1;" : "=f"(y) : "f"(x)); return y;
}

// GEMV for one row: k split across 8 lanes (kl), result reduced into lanes kl==0.
__device__ __forceinline__ void gemv_row(const float4* __restrict__ hp,
                                         const float* __restrict__ Wsm,
                                         int kl, float acc[CC])
{
#pragma unroll
    for (int c = 0; c < CC; c++) acc[c] = 0.0f;
#pragma unroll 4
    for (int i = 0; i < 24; i++) {
        float4 h = hp[i * 8 + kl];
#pragma unroll
        for (int c = 0; c < CC; c++) {
            const float4 w = *(const float4*)&Wsm[c * HH + i * 32 + kl * 4];
            acc[c] = fmaf(h.x, w.x, acc[c]);
            acc[c] = fmaf(h.y, w.y, acc[c]);
            acc[c] = fmaf(h.z, w.z, acc[c]);
            acc[c] = fmaf(h.w, w.w, acc[c]);
        }
    }
    // reduce within each 8-lane octet
#pragma unroll
    for (int off = 4; off > 0; off >>= 1)
#pragma unroll
        for (int c = 0; c < CC; c++)
            acc[c] += __shfl_xor_sync(FULLMASK, acc[c], off);
}

// ---------------------------------------------------------------------------
// Kernel A: fused emissions GEMV + chunk scan + numerator partials.
// Blocks 0..255: scan work (block -> batch b = blk/4, 8 warps, warp = 16 rows,
//   2 chunks of 8 steps). Blocks 256,257: t=0 emission rows.
// ---------------------------------------------------------------------------
__global__ __launch_bounds__(256, 2) void fused_kernel(
    const float* __restrict__ hidden,
    const float* __restrict__ W,
    const float* __restrict__ bias,
    const float* __restrict__ trv,
    const int*   __restrict__ tags,
    const int*   __restrict__ mask)
{
    __shared__ alignas(16) float Wsm[CC * HH];      // 27648 B
    __shared__ alignas(16) float Te_sm[CC][12];     // exp(tr), padded rows
    __shared__ alignas(16) float tr_sm[81];
    __shared__ float bias_sm[CC];
    __shared__ alignas(16) float em_sm[8][16][12];  // per-warp emissions

    const int tid  = threadIdx.x;
    const int wid  = tid >> 5;
    const int lane = tid & 31;

    for (int i = tid; i < CC * HH / 4; i += 256)
        ((float4*)Wsm)[i] = ((const float4*)W)[i];
    if (tid < 81) {
        float t = trv[tid];
        tr_sm[tid] = t;
        Te_sm[tid / 9][tid % 9] = ex2f(t * L2E);
    }
    if (tid < CC) bias_sm[tid] = bias[tid];
    __syncthreads();

    const int o  = lane >> 3;   // row-in-group / octet
    const int kl = lane & 7;    // k-slice within octet

    if (blockIdx.x >= 256) {
        // ---- t=0 emission rows: 2 blocks x 8 warps x 4 rows = 64 ----
        const int bb = (blockIdx.x - 256) * 32 + wid * 4 + o;
        const float4* hp = (const float4*)(hidden + (size_t)bb * SS * HH);
        float acc[CC];
        gemv_row(hp, Wsm, kl, acc);
        if (kl == 0) {
#pragma unroll
            for (int c = 0; c < CC; c++)
                g_emis0[bb * CC + c] = acc[c] + bias_sm[c];
        }
        return;
    }

    const int b  = blockIdx.x >> 2;
    const int wb = ((blockIdx.x & 3) << 3) | wid;   // warp-in-batch 0..31
    const int tw = 1 + wb * 16;                      // first t of window

    // sequence length (mask is a prefix of ones)
    int len = 0;
    {
        const int* mrow = mask + (size_t)b * SS;
        for (int t = lane; t < SS; t += 32) len += mrow[t];
#pragma unroll
        for (int off = 16; off > 0; off >>= 1)
            len += __shfl_xor_sync(FULLMASK, len, off);
    }

    // ---- GEMV: 16 rows in 4 groups of 4 ----
#pragma unroll 1
    for (int g = 0; g < 4; g++) {
        const int t    = tw + g * 4 + o;
        const int rowc = (t < SS) ? t : (SS - 1);   // clamp (t=512 edge)
        const float4* hp = (const float4*)(hidden + ((size_t)b * SS + rowc) * HH);
        float acc[CC];
        gemv_row(hp, Wsm, kl, acc);
        if (kl == 0) {
#pragma unroll
            for (int c = 0; c < CC; c++)
                em_sm[wid][g * 4 + o][c] = acc[c] + bias_sm[c];
        }
    }
    __syncwarp();

    // ---- numerator partial over this window ----
    float np = 0.0f;
    if (lane < 16) {
        const int t = tw + lane;
        if (t < len) {
            const int tp = tags[(size_t)b * SS + t - 1];
            const int tc = tags[(size_t)b * SS + t];
            np = tr_sm[tp * CC + tc] + em_sm[wid][lane][tc];
        }
    }
#pragma unroll
    for (int off = 16; off > 0; off >>= 1)
        np += __shfl_xor_sync(FULLMASK, np, off);
    if (lane == 0) g_num[b * WPBATCH + wb] = np;

    // ---- chunk scan: lane (s, r); s = sub-chunk, r = matrix row ----
    const int  ls     = (lane < 18) ? lane : 17;
    const int  s      = ls / 9;
    const int  r      = ls - s * 9;
    const bool active = (lane < 18);

    float m[CC];
#pragma unroll
    for (int c = 0; c < CC; c++) m[c] = (c == r) ? 1.0f : 0.0f;
    int esum = 0;
    const int tbase = tw + s * CH;

#pragma unroll 1
    for (int i = 0; i < CH; i++) {
        const int widx = s * CH + i;
        const int t    = tbase + i;
        const float4 e0 = *(const float4*)&em_sm[wid][widx][0];
        const float4 e1 = *(const float4*)&em_sm[wid][widx][4];
        const float  e8 = em_sm[wid][widx][8];
        float eml[CC];
        eml[0] = ex2f(e0.x * L2E); eml[1] = ex2f(e0.y * L2E);
        eml[2] = ex2f(e0.z * L2E); eml[3] = ex2f(e0.w * L2E);
        eml[4] = ex2f(e1.x * L2E); eml[5] = ex2f(e1.y * L2E);
        eml[6] = ex2f(e1.z * L2E); eml[7] = ex2f(e1.w * L2E);
        eml[8] = ex2f(e8 * L2E);

        float v[CC];
#pragma unroll
        for (int c = 0; c < CC; c++) v[c] = 0.0f;
#pragma unroll
        for (int j = 0; j < CC; j++) {
            const float4 ta = *(const float4*)&Te_sm[j][0];
            const float4 tb = *(const float4*)&Te_sm[j][4];
            const float  t8 = Te_sm[j][8];
            const float  mj = m[j];
            v[0] = fmaf(mj, ta.x, v[0]); v[1] = fmaf(mj, ta.y, v[1]);
            v[2] = fmaf(mj, ta.z, v[2]); v[3] = fmaf(mj, ta.w, v[3]);
            v[4] = fmaf(mj, tb.x, v[4]); v[5] = fmaf(mj, tb.y, v[5]);
            v[6] = fmaf(mj, tb.z, v[6]); v[7] = fmaf(mj, tb.w, v[7]);
            v[8] = fmaf(mj, t8, v[8]);
        }
#pragma unroll
        for (int c = 0; c < CC; c++) v[c] *= eml[c];

        float mx01 = fmaxf(v[0], v[1]), mx23 = fmaxf(v[2], v[3]);
        float mx45 = fmaxf(v[4], v[5]), mx67 = fmaxf(v[6], v[7]);
        float mx = fmaxf(fmaxf(fmaxf(mx01, mx23), fmaxf(mx45, mx67)), v[8]);
        const int   eb  = (__float_as_int(mx) >> 23) & 0xff;
        const float pot = __int_as_float((254 - eb) << 23);
        const bool  act = (t < len);
#pragma unroll
        for (int c = 0; c < CC; c++) m[c] = act ? v[c] * pot : m[c];
        esum += act ? (eb - 127) : 0;
    }

    if (active) {
        const int k = wb * 2 + s;
        float* dst = g_P + ((size_t)b * KCH + k) * 81 + r * 9;
#pragma unroll
        for (int c = 0; c < CC; c++) dst[c] = m[c];
        g_esum[((size_t)b * KCH + k) * CC + r] = esum;
    }
}

// ---------------------------------------------------------------------------
// Kernel B: per-batch combine (smem-staged chunk matrices) + denominator +
// numerator assembly + atomic mean -> out.
// ---------------------------------------------------------------------------
__global__ __launch_bounds__(128) void combine_kernel(
    const float* __restrict__ stv,
    const float* __restrict__ etv,
    const int*   __restrict__ tags,
    const int*   __restrict__ mask,
    float* __restrict__ out)
{
    __shared__ alignas(16) float P_sm[KCH * 81];    // 20736 B
    __shared__ int E_sm[KCH * CC];                  // 2304 B
    __shared__ int len_sm;

    const int b    = blockIdx.x;
    const int tid  = threadIdx.x;
    const int wid  = tid >> 5;
    const int lane = tid & 31;

    for (int i = tid; i < KCH * 81 / 4; i += 128)
        ((float4*)P_sm)[i] = ((const float4*)(g_P + (size_t)b * KCH * 81))[i];
    for (int i = tid; i < KCH * CC; i += 128)
        E_sm[i] = g_esum[(size_t)b * KCH * CC + i];
    if (wid == 1) {
        int mc = 0;
        const int* mrow = mask + (size_t)b * SS;
        for (int t = lane; t < SS; t += 32) mc += mrow[t];
#pragma unroll
        for (int off = 16; off > 0; off >>= 1)
            mc += __shfl_xor_sync(FULLMASK, mc, off);
        if (lane == 0) len_sm = mc;
    }
    __syncthreads();
    if (wid != 0) return;

    const int  len = len_sm;
    const int  c   = (lane < CC) ? lane : 0;
    const bool on  = (lane < CC);

    float a = on ? ex2f((stv[c] + g_emis0[b * CC + c]) * L2E) : 0.0f;
    int E = 0;

#pragma unroll 1
    for (int k = 0; k < KCH; k++) {
        int ej = on ? E_sm[k * CC + lane] : (int)0xC0000000;
        int emax = ej;
#pragma unroll
        for (int off = 16; off > 0; off >>= 1)
            emax = max(emax, __shfl_xor_sync(FULLMASK, emax, off));
        const int d = ej - emax;
        const float sc = (d > -126) ? __int_as_float((d + 127) << 23) : 0.0f;
        const float ap = a * sc;
        E += emax;

        float na = 0.0f;
        const float* Pk = P_sm + k * 81;
#pragma unroll
        for (int j = 0; j < CC; j++) {
            const float sj = __shfl_sync(FULLMASK, ap, j);
            na = fmaf(sj, Pk[j * 9 + c], na);
        }
        na = on ? na : 0.0f;

        float mxa = na;
#pragma unroll
        for (int off = 16; off > 0; off >>= 1)
            mxa = fmaxf(mxa, __shfl_xor_sync(FULLMASK, mxa, off));
        const int   eb  = (__float_as_int(mxa) >> 23) & 0xff;
        const float pot = __int_as_float((254 - eb) << 23);
        a = na * pot;
        E += eb - 127;
    }

    float term = on ? a * ex2f(etv[c] * L2E) : 0.0f;
#pragma unroll
    for (int off = 16; off > 0; off >>= 1)
        term += __shfl_xor_sync(FULLMASK, term, off);
    const float denom = (lg2f(term) + (float)E) * LN2;

    float np = (lane < WPBATCH) ? g_num[b * WPBATCH + lane] : 0.0f;
#pragma unroll
    for (int off = 16; off > 0; off >>= 1)
        np += __shfl_xor_sync(FULLMASK, np, off);
    const int first = tags[(size_t)b * SS];
    const int last  = tags[(size_t)b * SS + len - 1];
    const float num = np + stv[first] + g_emis0[b * CC + first] + etv[last];
    const float llh = num - denom;

    if (lane == 0) {
        atomicAdd(&g_acc, llh);
        __threadfence();
        const int cnt = atomicAdd(&g_cnt, 1);
        if (cnt == BB - 1) {
            __threadfence();
            const float total = atomicAdd(&g_acc, 0.0f);
            out[0] = -total * (1.0f / (float)BB);
            g_acc = 0.0f;   // reset for next graph replay
            g_cnt = 0;
        }
    }
}

// ---------------------------------------------------------------------------
extern "C" void kernel_launch(void* const* d_in, const int* in_sizes, int n_in,
                              void* d_out, int out_size)
{
    (void)in_sizes; (void)n_in; (void)out_size;
    const float* hidden = (const float*)d_in[0];
    const float* W      = (const float*)d_in[1];
    const float* bias   = (const float*)d_in[2];
    const float* stv    = (const float*)d_in[3];
    const float* trv    = (const float*)d_in[4];
    const float* etv    = (const float*)d_in[5];
    const int*   tags   = (const int*)d_in[6];
    const int*   mask   = (const int*)d_in[7];

    fused_kernel<<<258, 256>>>(hidden, W, bias, trv, tags, mask);
    combine_kernel<<<BB, 128>>>(stv, etv, tags, mask, (float*)d_out);
}

// round 6
// speedup vs baseline: 1.3842x; 1.3842x over previous
#include <cuda_runtime.h>

#define BB 64
#define SS 512
#define HH 768
#define CC 9
#define KCH 24       // chunks per batch
#define CH  22       // steps per chunk (24*22 = 528 >= 511)
#define L2E 1.4426950408889634f
#define LN2 0.6931471805599453f
#define FULLMASK 0xffffffffu

// scratch (no allocations allowed)
__device__ __align__(16) float g_emis[BB * SS * CC];   // 1.18 MB
__device__ float g_acc = 0.0f;
__device__ int   g_cnt = 0;

__device__ __forceinline__ float ex2f(float x) {
    float y; asm("ex2.approx.ftz.f32 %0, %1;" : "=f"(y) : "f"(x)); return y;
}
__device__ __forceinline__ float lg2f(float x) {
    float y; asm("lg2.approx.ftz.f32 %0, %1;" : "=f"(y) : "f"(x)); return y;
}

// ---------------------------------------------------------------------------
// Kernel 1: emissions = hidden @ W^T + b.
// 4 rows per warp (halved W-LDS per row), unroll 3 (12 LDGs in flight).
// ---------------------------------------------------------------------------
__global__ __launch_bounds__(256, 2) void emis_kernel(
    const float* __restrict__ hidden,
    const float* __restrict__ W,
    const float* __restrict__ bias)
{
    __shared__ alignas(16) float Wsm[CC * HH];   // 27648 B
    for (int i = threadIdx.x; i < CC * HH / 4; i += 256)
        ((float4*)Wsm)[i] = ((const float4*)W)[i];
    __syncthreads();

    float bv[CC];
#pragma unroll
    for (int c = 0; c < CC; c++) bv[c] = bias[c];

    const int lane   = threadIdx.x & 31;
    const int warp   = (blockIdx.x * blockDim.x + threadIdx.x) >> 5;
    const int nwarps = gridDim.x * (blockDim.x >> 5);
    const int NGROUPS = (BB * SS) / 4;   // 8192 groups of 4 rows

    for (int g = warp; g < NGROUPS; g += nwarps) {
        const int row0 = g * 4;
        const float4* hp0 = (const float4*)(hidden + (size_t)row0 * HH);
        const float4* hp1 = (const float4*)(hidden + (size_t)(row0 + 1) * HH);
        const float4* hp2 = (const float4*)(hidden + (size_t)(row0 + 2) * HH);
        const float4* hp3 = (const float4*)(hidden + (size_t)(row0 + 3) * HH);

        float acc[4][CC];
#pragma unroll
        for (int r = 0; r < 4; r++)
#pragma unroll
            for (int c = 0; c < CC; c++) acc[r][c] = 0.0f;

#pragma unroll 3
        for (int i = 0; i < HH / 128; i++) {   // 6 iterations
            float4 h[4];
            h[0] = hp0[i * 32 + lane];
            h[1] = hp1[i * 32 + lane];
            h[2] = hp2[i * 32 + lane];
            h[3] = hp3[i * 32 + lane];
#pragma unroll
            for (int c = 0; c < CC; c++) {
                const float4 w = ((const float4*)(Wsm + c * HH))[i * 32 + lane];
#pragma unroll
                for (int r = 0; r < 4; r++) {
                    acc[r][c] = fmaf(h[r].x, w.x, acc[r][c]);
                    acc[r][c] = fmaf(h[r].y, w.y, acc[r][c]);
                    acc[r][c] = fmaf(h[r].z, w.z, acc[r][c]);
                    acc[r][c] = fmaf(h[r].w, w.w, acc[r][c]);
                }
            }
        }
#pragma unroll
        for (int r = 0; r < 4; r++)
#pragma unroll
            for (int c = 0; c < CC; c++)
#pragma unroll
                for (int off = 16; off > 0; off >>= 1)
                    acc[r][c] += __shfl_xor_sync(FULLMASK, acc[r][c], off);

        if (lane == 0) {
#pragma unroll
            for (int r = 0; r < 4; r++)
#pragma unroll
                for (int c = 0; c < CC; c++)
                    g_emis[(size_t)(row0 + r) * CC + c] = acc[r][c] + bv[c];
        }
    }
}

// ---------------------------------------------------------------------------
// Kernel 2: full CRF per batch in ONE block (64 blocks x 256 threads).
// Phase 1: 8 warps compute 24 chunk matrix products into smem (+ numerator
//   partials). Lane = (s, r): sub-chunk s in {0,1,2}, matrix row r.
// Phase 2: warp 0 combines the 24 chunks (smem-resident), computes llh,
//   atomic-accumulates the mean into out.
// ---------------------------------------------------------------------------
__global__ __launch_bounds__(256) void crf_kernel(
    const float* __restrict__ stv,
    const float* __restrict__ trv,
    const float* __restrict__ etv,
    const int*   __restrict__ tags,
    const int*   __restrict__ mask,
    float* __restrict__ out)
{
    __shared__ float em_sm[8][3 * CH * CC];   // 8 x 594 floats = 19008 B
    __shared__ float P_sm[KCH * 81];          // 7776 B
    __shared__ int   E_sm[KCH * CC];          // 864 B
    __shared__ float num_sm[8];
    __shared__ float Te_sh[81], tr_sh[81];

    const int b    = blockIdx.x;
    const int tid  = threadIdx.x;
    const int wid  = tid >> 5;
    const int lane = tid & 31;

    if (tid < 81) {
        const float t = trv[tid];
        tr_sh[tid] = t;
        Te_sh[tid] = ex2f(t * L2E);
    }
    __syncthreads();

    // Te into registers (smem broadcast reads)
    float Te[81];
#pragma unroll
    for (int jc = 0; jc < 81; jc++) Te[jc] = Te_sh[jc];

    // sequence length (mask is a prefix of ones)
    int len = 0;
    {
        const int* mrow = mask + (size_t)b * SS;
        for (int t = lane; t < SS; t += 32) len += mrow[t];
#pragma unroll
        for (int off = 16; off > 0; off >>= 1)
            len += __shfl_xor_sync(FULLMASK, len, off);
    }

    // ---- stage this warp's emission window [tb, tb+66) ----
    const int tb = 1 + 3 * CH * wid;
    {
        const float* src = g_emis + ((size_t)b * SS + tb) * CC;
        for (int idx = lane; idx < 3 * CH * CC; idx += 32) {
            const int tt = tb + idx / CC;
            em_sm[wid][idx] = (tt < SS) ? src[idx] : 0.0f;
        }
    }
    __syncwarp();

    // ---- numerator partial ----
    float np = 0.0f;
    for (int i = lane; i < 3 * CH; i += 32) {
        const int t = tb + i;
        if (t < len) {
            const int tp = tags[(size_t)b * SS + t - 1];
            const int tc = tags[(size_t)b * SS + t];
            np += tr_sh[tp * CC + tc] + em_sm[wid][i * CC + tc];
        }
    }
#pragma unroll
    for (int off = 16; off > 0; off >>= 1)
        np += __shfl_xor_sync(FULLMASK, np, off);
    if (lane == 0) num_sm[wid] = np;

    // ---- chunk matrix product: lane (s, r) ----
    const int  ls     = (lane < 27) ? lane : 26;
    const int  s      = ls / 9;
    const int  r      = ls - s * 9;
    const bool active = (lane < 27);

    float m[CC];
#pragma unroll
    for (int c = 0; c < CC; c++) m[c] = (c == r) ? 1.0f : 0.0f;
    int esum = 0;
    const int tbase = tb + s * CH;

#pragma unroll 1
    for (int i = 0; i < CH; i++) {
        const int t = tbase + i;
        const float* em = &em_sm[wid][(s * CH + i) * CC];
        float eml[CC];
#pragma unroll
        for (int c = 0; c < CC; c++) eml[c] = ex2f(em[c] * L2E);

        float v[CC];
#pragma unroll
        for (int c = 0; c < CC; c++) v[c] = m[0] * Te[0 * 9 + c];
#pragma unroll
        for (int j = 1; j < CC; j++)
#pragma unroll
            for (int c = 0; c < CC; c++)
                v[c] = fmaf(m[j], Te[j * 9 + c], v[c]);
#pragma unroll
        for (int c = 0; c < CC; c++) v[c] *= eml[c];

        float mx01 = fmaxf(v[0], v[1]), mx23 = fmaxf(v[2], v[3]);
        float mx45 = fmaxf(v[4], v[5]), mx67 = fmaxf(v[6], v[7]);
        float mx = fmaxf(fmaxf(fmaxf(mx01, mx23), fmaxf(mx45, mx67)), v[8]);
        const int   eb  = (__float_as_int(mx) >> 23) & 0xff;
        const float pot = __int_as_float((254 - eb) << 23);
        const bool  act = (t < len);
#pragma unroll
        for (int c = 0; c < CC; c++) m[c] = act ? v[c] * pot : m[c];
        esum += act ? (eb - 127) : 0;
    }

    if (active) {
        const int k = 3 * wid + s;
        float* dst = P_sm + k * 81 + r * 9;
#pragma unroll
        for (int c = 0; c < CC; c++) dst[c] = m[c];
        E_sm[k * CC + r] = esum;
    }
    __syncthreads();

    if (wid != 0) return;

    // ---- per-chunk emax, precomputed in parallel (lane k < 24) ----
    int my_emax = (int)0xC0000000;
    if (lane < KCH) {
        my_emax = E_sm[lane * CC];
#pragma unroll
        for (int r2 = 1; r2 < CC; r2++)
            my_emax = max(my_emax, E_sm[lane * CC + r2]);
    }

    // ---- combine: a (unnormalized), true alpha = a * 2^E ----
    const int  c  = (lane < CC) ? lane : 0;
    const bool on = (lane < CC);
    float a = on ? ex2f((stv[c] + g_emis[(size_t)b * SS * CC + c]) * L2E) : 0.0f;
    int E = 0;

#pragma unroll 1
    for (int k = 0; k < KCH; k++) {
        const int emk = __shfl_sync(FULLMASK, my_emax, k);
        const int ej  = on ? E_sm[k * CC + lane] : emk;
        const int d   = ej - emk;                     // <= 0
        const float asc = (d > -126) ? a * __int_as_float((d + 127) << 23) : 0.0f;

        const float s0 = __shfl_sync(FULLMASK, asc, 0);
        const float s1 = __shfl_sync(FULLMASK, asc, 1);
        const float s2 = __shfl_sync(FULLMASK, asc, 2);
        const float s3 = __shfl_sync(FULLMASK, asc, 3);
        const float s4 = __shfl_sync(FULLMASK, asc, 4);
        const float s5 = __shfl_sync(FULLMASK, asc, 5);
        const float s6 = __shfl_sync(FULLMASK, asc, 6);
        const float s7 = __shfl_sync(FULLMASK, asc, 7);
        const float s8 = __shfl_sync(FULLMASK, asc, 8);

        // renorm scale from lane 0's exponent (s0 > 0 always)
        const int   e0 = (((__float_as_int(s0) >> 23) & 0xff)) - 127;
        const float sc = __int_as_float((127 - e0) << 23);   // 2^{-e0}

        const float* Pk = P_sm + k * 81;
        float p0 = s0 * Pk[0 * 9 + c], p1 = s1 * Pk[1 * 9 + c];
        float p2 = s2 * Pk[2 * 9 + c], p3 = s3 * Pk[3 * 9 + c];
        float p4 = s4 * Pk[4 * 9 + c], p5 = s5 * Pk[5 * 9 + c];
        float p6 = s6 * Pk[6 * 9 + c], p7 = s7 * Pk[7 * 9 + c];
        float p8 = s8 * Pk[8 * 9 + c];
        float q0 = p0 + p1, q1 = p2 + p3, q2 = p4 + p5, q3 = p6 + p7;
        const float na = ((q0 + q1) + (q2 + q3)) + p8;

        a = on ? na * sc : 0.0f;
        E += emk + e0;
    }

    // ---- denominator ----
    float term = on ? a * ex2f(etv[c] * L2E) : 0.0f;
#pragma unroll
    for (int off = 16; off > 0; off >>= 1)
        term += __shfl_xor_sync(FULLMASK, term, off);
    const float denom = (lg2f(term) + (float)E) * LN2;

    // ---- numerator assembly ----
    float nsum = (lane < 8) ? num_sm[lane] : 0.0f;
#pragma unroll
    for (int off = 16; off > 0; off >>= 1)
        nsum += __shfl_xor_sync(FULLMASK, nsum, off);
    const int first = tags[(size_t)b * SS];
    const int last  = tags[(size_t)b * SS + len - 1];
    const float num = nsum + stv[first]
                    + g_emis[(size_t)b * SS * CC + first] + etv[last];
    const float llh = num - denom;

    if (lane == 0) {
        atomicAdd(&g_acc, llh);
        __threadfence();
        const int cnt = atomicAdd(&g_cnt, 1);
        if (cnt == BB - 1) {
            __threadfence();
            const float total = atomicAdd(&g_acc, 0.0f);
            out[0] = -total * (1.0f / (float)BB);
            g_acc = 0.0f;   // reset for next graph replay
            g_cnt = 0;
        }
    }
}

// ---------------------------------------------------------------------------
extern "C" void kernel_launch(void* const* d_in, const int* in_sizes, int n_in,
                              void* d_out, int out_size)
{
    (void)in_sizes; (void)n_in; (void)out_size;
    const float* hidden = (const float*)d_in[0];
    const float* W      = (const float*)d_in[1];
    const float* bias   = (const float*)d_in[2];
    const float* stv    = (const float*)d_in[3];
    const float* trv    = (const float*)d_in[4];
    const float* etv    = (const float*)d_in[5];
    const int*   tags   = (const int*)d_in[6];
    const int*   mask   = (const int*)d_in[7];

    emis_kernel<<<296, 256>>>(hidden, W, bias);
    crf_kernel<<<BB, 256>>>(stv, trv, etv, tags, mask, (float*)d_out);
}

// round 7
// speedup vs baseline: 1.5439x; 1.1154x over previous
#include <cuda_runtime.h>

#define BB 64
#define SS 512
#define HH 768
#define CC 9
#define KCH 24       // chunks per batch
#define CH  22       // steps per chunk (24*22 = 528 >= 511)
#define L2E 1.4426950408889634f
#define LN2 0.6931471805599453f
#define FULLMASK 0xffffffffu

// scratch (no allocations allowed)
__device__ __align__(16) float g_emis[BB * SS * CC];   // 1.18 MB
__device__ float g_acc = 0.0f;
__device__ int   g_cnt = 0;

__device__ __forceinline__ float ex2f(float x) {
    float y; asm("ex2.approx.ftz.f32 %0, %1;" : "=f"(y) : "f"(x)); return y;
}
__device__ __forceinline__ float lg2f(float x) {
    float y; asm("lg2.approx.ftz.f32 %0, %1;" : "=f"(y) : "f"(x)); return y;
}

// ---------------------------------------------------------------------------
// Kernel 1: emissions = hidden @ W^T + b.
// 4 rows per warp, unroll 3 (12 LDGs in flight).
// ---------------------------------------------------------------------------
__global__ __launch_bounds__(256, 2) void emis_kernel(
    const float* __restrict__ hidden,
    const float* __restrict__ W,
    const float* __restrict__ bias)
{
    __shared__ alignas(16) float Wsm[CC * HH];   // 27648 B
    for (int i = threadIdx.x; i < CC * HH / 4; i += 256)
        ((float4*)Wsm)[i] = ((const float4*)W)[i];
    __syncthreads();

    float bv[CC];
#pragma unroll
    for (int c = 0; c < CC; c++) bv[c] = bias[c];

    const int lane   = threadIdx.x & 31;
    const int warp   = (blockIdx.x * blockDim.x + threadIdx.x) >> 5;
    const int nwarps = gridDim.x * (blockDim.x >> 5);
    const int NGROUPS = (BB * SS) / 4;   // 8192 groups of 4 rows

    for (int g = warp; g < NGROUPS; g += nwarps) {
        const int row0 = g * 4;
        const float4* hp0 = (const float4*)(hidden + (size_t)row0 * HH);
        const float4* hp1 = (const float4*)(hidden + (size_t)(row0 + 1) * HH);
        const float4* hp2 = (const float4*)(hidden + (size_t)(row0 + 2) * HH);
        const float4* hp3 = (const float4*)(hidden + (size_t)(row0 + 3) * HH);

        float acc[4][CC];
#pragma unroll
        for (int r = 0; r < 4; r++)
#pragma unroll
            for (int c = 0; c < CC; c++) acc[r][c] = 0.0f;

#pragma unroll 3
        for (int i = 0; i < HH / 128; i++) {   // 6 iterations
            float4 h[4];
            h[0] = hp0[i * 32 + lane];
            h[1] = hp1[i * 32 + lane];
            h[2] = hp2[i * 32 + lane];
            h[3] = hp3[i * 32 + lane];
#pragma unroll
            for (int c = 0; c < CC; c++) {
                const float4 w = ((const float4*)(Wsm + c * HH))[i * 32 + lane];
#pragma unroll
                for (int r = 0; r < 4; r++) {
                    acc[r][c] = fmaf(h[r].x, w.x, acc[r][c]);
                    acc[r][c] = fmaf(h[r].y, w.y, acc[r][c]);
                    acc[r][c] = fmaf(h[r].z, w.z, acc[r][c]);
                    acc[r][c] = fmaf(h[r].w, w.w, acc[r][c]);
                }
            }
        }
#pragma unroll
        for (int r = 0; r < 4; r++)
#pragma unroll
            for (int c = 0; c < CC; c++)
#pragma unroll
                for (int off = 16; off > 0; off >>= 1)
                    acc[r][c] += __shfl_xor_sync(FULLMASK, acc[r][c], off);

        if (lane == 0) {
#pragma unroll
            for (int r = 0; r < 4; r++)
#pragma unroll
                for (int c = 0; c < CC; c++)
                    g_emis[(size_t)(row0 + r) * CC + c] = acc[r][c] + bv[c];
        }
    }
}

// ---------------------------------------------------------------------------
// Kernel 2: full CRF per batch in ONE block (64 blocks x 256 threads).
// Phase 1: 8 warps, lane = (s, r): sub-chunk s in {0,1,2}, row r. Emissions
//   pre-exponentiated at staging (padded stride 12); Te read j-outer from
//   smem (3x LDS.128, broadcast) -> ~40 live regs, no spills.
// Phase 2: warp 0 combines chunks (early-exit past len), llh, atomic mean.
// ---------------------------------------------------------------------------
__global__ __launch_bounds__(256) void crf_kernel(
    const float* __restrict__ stv,
    const float* __restrict__ trv,
    const float* __restrict__ etv,
    const int*   __restrict__ tags,
    const int*   __restrict__ mask,
    float* __restrict__ out)
{
    __shared__ alignas(16) float eml_sm[8][3 * CH * 12];  // exp(em), 25344 B
    __shared__ alignas(16) float Te_sm[CC][12];           // exp(tr) rows, padded
    __shared__ alignas(16) float P_sm[KCH * 81];          // 7776 B
    __shared__ int   E_sm[KCH * CC];                      // 864 B
    __shared__ float tr_sh[81];
    __shared__ float num_sm[8];

    const int b    = blockIdx.x;
    const int tid  = threadIdx.x;
    const int wid  = tid >> 5;
    const int lane = tid & 31;

    if (tid < 81) {
        const float t = trv[tid];
        tr_sh[tid] = t;
        Te_sm[tid / 9][tid % 9] = ex2f(t * L2E);
    }
    __syncthreads();

    // sequence length (mask is a prefix of ones)
    int len = 0;
    {
        const int* mrow = mask + (size_t)b * SS;
        for (int t = lane; t < SS; t += 32) len += mrow[t];
#pragma unroll
        for (int off = 16; off > 0; off >>= 1)
            len += __shfl_xor_sync(FULLMASK, len, off);
    }

    // ---- stage exp(emissions) for window [tb, tb+66), padded stride 12 ----
    const int tb = 1 + 3 * CH * wid;
    {
        const float* src = g_emis + ((size_t)b * SS + tb) * CC;
#pragma unroll 4
        for (int idx = lane; idx < 3 * CH * CC; idx += 32) {
            const int stp = idx / CC;
            const int cc  = idx - stp * CC;
            const int tt  = tb + stp;
            const float raw = ((tt < SS) && (tt < len)) ? src[idx] : 0.0f;
            eml_sm[wid][stp * 12 + cc] = ex2f(raw * L2E);
        }
    }
    __syncwarp();

    // ---- numerator partial (raw emissions straight from gmem) ----
    float np = 0.0f;
    for (int i = lane; i < 3 * CH; i += 32) {
        const int t = tb + i;
        if (t < len) {
            const int tp = tags[(size_t)b * SS + t - 1];
            const int tc = tags[(size_t)b * SS + t];
            np += tr_sh[tp * CC + tc] + g_emis[((size_t)b * SS + t) * CC + tc];
        }
    }
#pragma unroll
    for (int off = 16; off > 0; off >>= 1)
        np += __shfl_xor_sync(FULLMASK, np, off);
    if (lane == 0) num_sm[wid] = np;

    // ---- chunk matrix product: lane (s, r) ----
    const int ls = (lane < 27) ? lane : 26;
    const int s  = ls / 9;
    const int r  = ls - s * 9;

    float m[CC];
#pragma unroll
    for (int c = 0; c < CC; c++) m[c] = (c == r) ? 1.0f : 0.0f;
    int esum = 0;
    const int tbase = tb + s * CH;

#pragma unroll 1
    for (int i = 0; i < CH; i++) {
        if (tbase + i >= len) break;
        const float* emlrow = &eml_sm[wid][(s * CH + i) * 12];
        const float4 e0 = *(const float4*)&emlrow[0];
        const float4 e1 = *(const float4*)&emlrow[4];
        const float  e8 = emlrow[8];

        float v[CC];
#pragma unroll
        for (int c = 0; c < CC; c++) v[c] = 0.0f;
#pragma unroll
        for (int j = 0; j < CC; j++) {
            const float4 t0 = *(const float4*)&Te_sm[j][0];
            const float4 t1 = *(const float4*)&Te_sm[j][4];
            const float  t8 = Te_sm[j][8];
            const float  mj = m[j];
            v[0] = fmaf(mj, t0.x, v[0]); v[1] = fmaf(mj, t0.y, v[1]);
            v[2] = fmaf(mj, t0.z, v[2]); v[3] = fmaf(mj, t0.w, v[3]);
            v[4] = fmaf(mj, t1.x, v[4]); v[5] = fmaf(mj, t1.y, v[5]);
            v[6] = fmaf(mj, t1.z, v[6]); v[7] = fmaf(mj, t1.w, v[7]);
            v[8] = fmaf(mj, t8, v[8]);
        }
        v[0] *= e0.x; v[1] *= e0.y; v[2] *= e0.z; v[3] *= e0.w;
        v[4] *= e1.x; v[5] *= e1.y; v[6] *= e1.z; v[7] *= e1.w;
        v[8] *= e8;

        float mx01 = fmaxf(v[0], v[1]), mx23 = fmaxf(v[2], v[3]);
        float mx45 = fmaxf(v[4], v[5]), mx67 = fmaxf(v[6], v[7]);
        float mx = fmaxf(fmaxf(fmaxf(mx01, mx23), fmaxf(mx45, mx67)), v[8]);
        const int   eb  = (__float_as_int(mx) >> 23) & 0xff;
        const float pot = __int_as_float((254 - eb) << 23);
#pragma unroll
        for (int c = 0; c < CC; c++) m[c] = v[c] * pot;
        esum += eb - 127;
    }

    if (lane < 27) {
        const int k = 3 * wid + s;
        float* dst = P_sm + k * 81 + r * 9;
#pragma unroll
        for (int c = 0; c < CC; c++) dst[c] = m[c];
        E_sm[k * CC + r] = esum;
    }
    __syncthreads();

    if (wid != 0) return;

    // ---- per-chunk emax, precomputed in parallel (lane k < 24) ----
    int my_emax = (int)0xC0000000;
    if (lane < KCH) {
        my_emax = E_sm[lane * CC];
#pragma unroll
        for (int r2 = 1; r2 < CC; r2++)
            my_emax = max(my_emax, E_sm[lane * CC + r2]);
    }

    // ---- combine: a (unnormalized), true alpha = a * 2^E ----
    const int  c  = (lane < CC) ? lane : 0;
    const bool on = (lane < CC);
    float a = on ? ex2f((stv[c] + g_emis[(size_t)b * SS * CC + c]) * L2E) : 0.0f;
    int E = 0;

#pragma unroll 1
    for (int k = 0; k < KCH; k++) {
        if (1 + k * CH >= len) break;   // identity chunks beyond len

        const int emk = __shfl_sync(FULLMASK, my_emax, k);
        const int ej  = on ? E_sm[k * CC + lane] : emk;
        const int d   = ej - emk;                     // <= 0
        const float asc = (d > -126) ? a * __int_as_float((d + 127) << 23) : 0.0f;

        const float s0 = __shfl_sync(FULLMASK, asc, 0);
        const float s1 = __shfl_sync(FULLMASK, asc, 1);
        const float s2 = __shfl_sync(FULLMASK, asc, 2);
        const float s3 = __shfl_sync(FULLMASK, asc, 3);
        const float s4 = __shfl_sync(FULLMASK, asc, 4);
        const float s5 = __shfl_sync(FULLMASK, asc, 5);
        const float s6 = __shfl_sync(FULLMASK, asc, 6);
        const float s7 = __shfl_sync(FULLMASK, asc, 7);
        const float s8 = __shfl_sync(FULLMASK, asc, 8);

        // renorm scale from lane 0's exponent (s0 > 0 always)
        const int   e0 = (((__float_as_int(s0) >> 23) & 0xff)) - 127;
        const float sc = __int_as_float((127 - e0) << 23);   // 2^{-e0}

        const float* Pk = P_sm + k * 81;
        float p0 = s0 * Pk[0 * 9 + c], p1 = s1 * Pk[1 * 9 + c];
        float p2 = s2 * Pk[2 * 9 + c], p3 = s3 * Pk[3 * 9 + c];
        float p4 = s4 * Pk[4 * 9 + c], p5 = s5 * Pk[5 * 9 + c];
        float p6 = s6 * Pk[6 * 9 + c], p7 = s7 * Pk[7 * 9 + c];
        float p8 = s8 * Pk[8 * 9 + c];
        float q0 = p0 + p1, q1 = p2 + p3, q2 = p4 + p5, q3 = p6 + p7;
        const float na = ((q0 + q1) + (q2 + q3)) + p8;

        a = on ? na * sc : 0.0f;
        E += emk + e0;
    }

    // ---- denominator ----
    float term = on ? a * ex2f(etv[c] * L2E) : 0.0f;
#pragma unroll
    for (int off = 16; off > 0; off >>= 1)
        term += __shfl_xor_sync(FULLMASK, term, off);
    const float denom = (lg2f(term) + (float)E) * LN2;

    // ---- numerator assembly ----
    float nsum = (lane < 8) ? num_sm[lane] : 0.0f;
#pragma unroll
    for (int off = 16; off > 0; off >>= 1)
        nsum += __shfl_xor_sync(FULLMASK, nsum, off);
    const int first = tags[(size_t)b * SS];
    const int last  = tags[(size_t)b * SS + len - 1];
    const float num = nsum + stv[first]
                    + g_emis[(size_t)b * SS * CC + first] + etv[last];
    const float llh = num - denom;

    if (lane == 0) {
        atomicAdd(&g_acc, llh);
        __threadfence();
        const int cnt = atomicAdd(&g_cnt, 1);
        if (cnt == BB - 1) {
            __threadfence();
            const float total = atomicAdd(&g_acc, 0.0f);
            out[0] = -total * (1.0f / (float)BB);
            g_acc = 0.0f;   // reset for next graph replay
            g_cnt = 0;
        }
    }
}

// ---------------------------------------------------------------------------
extern "C" void kernel_launch(void* const* d_in, const int* in_sizes, int n_in,
                              void* d_out, int out_size)
{
    (void)in_sizes; (void)n_in; (void)out_size;
    const float* hidden = (const float*)d_in[0];
    const float* W      = (const float*)d_in[1];
    const float* bias   = (const float*)d_in[2];
    const float* stv    = (const float*)d_in[3];
    const float* trv    = (const float*)d_in[4];
    const float* etv    = (const float*)d_in[5];
    const int*   tags   = (const int*)d_in[6];
    const int*   mask   = (const int*)d_in[7];

    emis_kernel<<<296, 256>>>(hidden, W, bias);
    crf_kernel<<<BB, 256>>>(stv, trv, etv, tags, mask, (float*)d_out);
}